// round 6
// baseline (speedup 1.0000x reference)
#include <cuda_runtime.h>
#include <cstdint>

typedef unsigned long long ull;

#define HD 128
#define DD 256

// ---------- packed f32x2 helpers (Blackwell sm_100+) ----------
__device__ __forceinline__ void fma2(ull &d, ull a, ull b) {
    asm("fma.rn.f32x2 %0, %1, %2, %0;" : "+l"(d) : "l"(a), "l"(b));
}
__device__ __forceinline__ ull add2(ull a, ull b) {
    ull d; asm("add.rn.f32x2 %0, %1, %2;" : "=l"(d) : "l"(a), "l"(b)); return d;
}
__device__ __forceinline__ float2 unpack2(ull u) {
    float2 r; asm("mov.b64 {%0, %1}, %2;" : "=f"(r.x), "=f"(r.y) : "l"(u)); return r;
}
__device__ __forceinline__ float tanh_approx(float x) {
    float r; asm("tanh.approx.f32 %0, %1;" : "=f"(r) : "f"(x)); return r;
}

// ---------- Kernel 1: xW = input @ Wi^T + bi, written into out[S,128] ----------
__global__ void __launch_bounds__(128) gemm_xw_kernel(
    const float* __restrict__ X,   // [S, 256]
    const float* __restrict__ Wi,  // [128, 256]
    const float* __restrict__ bi,  // [128]
    float* __restrict__ out, int S)
{
    __shared__ __align__(16) float xs[32][DD];
    const int h  = threadIdx.x;
    const int s0 = blockIdx.x * 32;

    const float4* Xg  = (const float4*)(X + (size_t)s0 * DD);
    float4*       xs4 = (float4*)&xs[0][0];
#pragma unroll
    for (int i = 0; i < 16; i++) xs4[h + 128 * i] = Xg[h + 128 * i];
    __syncthreads();

    float acc[32];
#pragma unroll
    for (int s = 0; s < 32; s++) acc[s] = 0.f;

    const float4* wr = (const float4*)(Wi + h * DD);
#pragma unroll 4
    for (int kk = 0; kk < DD / 4; kk++) {
        float4 wv = wr[kk];
#pragma unroll
        for (int s = 0; s < 32; s++) {
            float4 xv = *(const float4*)&xs[s][kk * 4];
            acc[s] = fmaf(wv.x, xv.x, acc[s]);
            acc[s] = fmaf(wv.y, xv.y, acc[s]);
            acc[s] = fmaf(wv.z, xv.z, acc[s]);
            acc[s] = fmaf(wv.w, xv.w, acc[s]);
        }
    }
    const float b = bi[h];
#pragma unroll
    for (int s = 0; s < 32; s++) out[(size_t)(s0 + s) * HD + h] = acc[s] + b;
}

// ---------- Kernel 2: sequential recurrence ----------
// 256 threads = 8 warps = 2 warps per SMSP (the co-resident warp hides
// LDS/MUFU latency). Lane pair (2u, 2u+1) of each warp shares output
// j = wrp*16 + u; each lane covers half of K (64 weights = 32 packed f32x2
// in registers). h double-buffered in shared; reads are broadcast LDS.128
// (16 lanes per address group). Reduce = 2-level f32x2 tree + one
// shfl_xor(1). tanh via single MUFU (tanh.approx). One __syncthreads per
// step; xw rows prefetched 8 steps ahead (L2-resident) with bias folded in;
// h stream overwrites consumed xw rows in d_out.
__global__ void __launch_bounds__(256, 1) rnn_seq_kernel(
    const float* __restrict__ Wh,  // [128, 128]
    const float* __restrict__ bh,  // [128]
    const float* __restrict__ h0,  // [1, 128]
    float* out,                    // [S, 128]: xw in, h out
    float* hn, int S, int has_hn)
{
    __shared__ __align__(16) float sh[2][HD];
    const int tid  = threadIdx.x;
    const int lane = tid & 31;
    const int wrp  = tid >> 5;
    const int half = lane & 1;
    const int j    = wrp * 16 + (lane >> 1);

    // Wh row j, half-K segment: 32 packed f32x2 in registers
    ull w[32];
    {
        const ulonglong2* wp = (const ulonglong2*)(Wh + j * HD + half * 64);
#pragma unroll
        for (int i = 0; i < 16; i++) { ulonglong2 v = wp[i]; w[2*i] = v.x; w[2*i+1] = v.y; }
    }
    const float bj = bh[j];

    if (tid < HD) sh[0][tid] = h0[tid];

    float xwb[8], xwn[8];
#pragma unroll
    for (int q = 0; q < 8; q++) xwb[q] = out[q * HD + j] + bj;

    __syncthreads();

    for (int t = 0; t < S; t += 8) {
        // prefetch the next 8 xw rows (consumed next outer iteration)
#pragma unroll
        for (int q = 0; q < 8; q++) {
            int tn = t + 8 + q;
            xwn[q] = (tn < S) ? out[(size_t)tn * HD + j] : 0.f;
        }
#pragma unroll
        for (int q = 0; q < 8; q++) {
            const int buf  = q & 1;         // t % 8 == 0, so step parity == q parity
            const int nbuf = buf ^ 1;
            const ulonglong2* hp = (const ulonglong2*)(&sh[buf][half * 64]);

            ull a0 = 0, a1 = 0, a2 = 0, a3 = 0;
#pragma unroll
            for (int i = 0; i < 8; i++) {
                ulonglong2 v0 = hp[2*i + 0];
                ulonglong2 v1 = hp[2*i + 1];
                fma2(a0, w[4*i + 0], v0.x);
                fma2(a1, w[4*i + 1], v0.y);
                fma2(a2, w[4*i + 2], v1.x);
                fma2(a3, w[4*i + 3], v1.y);
            }
            // 2-level packed reduce, horizontal add, partner exchange
            float2 rr = unpack2(add2(add2(a0, a1), add2(a2, a3)));
            float part = rr.x + rr.y;
            part += __shfl_xor_sync(0xFFFFFFFFu, part, 1);
            float z = part + xwb[q];

            float hval = tanh_approx(z);

            if (half == 0) sh[nbuf][j] = hval;            // publish h_t
            else           out[(size_t)(t + q) * HD + j] = hval; // stream to gmem
            __syncthreads();
        }
#pragma unroll
        for (int q = 0; q < 8; q++) xwb[q] = xwn[q] + bj;
    }

    if (has_hn && half == 0) hn[j] = sh[S & 1][j];
}

// ---------- launcher ----------
extern "C" void kernel_launch(void* const* d_in, const int* in_sizes, int n_in,
                              void* d_out, int out_size)
{
    (void)n_in;
    const float* input = (const float*)d_in[0];  // [S, 256]
    const float* h0    = (const float*)d_in[1];  // [1, 128]
    const float* Wi    = (const float*)d_in[2];  // [128, 256]
    const float* bi    = (const float*)d_in[3];  // [128]
    const float* Wh    = (const float*)d_in[4];  // [128, 128]
    const float* bh    = (const float*)d_in[5];  // [128]
    float* out = (float*)d_out;

    const int S = in_sizes[0] / DD;
    const int has_hn = (out_size >= S * HD + HD) ? 1 : 0;
    float* hn = out + (size_t)S * HD;

    gemm_xw_kernel<<<(S + 31) / 32, 128>>>(input, Wi, bi, out, S);
    rnn_seq_kernel<<<1, 256>>>(Wh, bh, h0, out, hn, S, has_hn);
}

// round 7
// speedup vs baseline: 1.6013x; 1.6013x over previous
#include <cuda_runtime.h>
#include <cstdint>

typedef unsigned long long ull;

#define HD 128
#define DD 256

// ---------- packed f32x2 helpers (Blackwell sm_100+) ----------
__device__ __forceinline__ void fma2(ull &d, ull a, ull b) {
    asm("fma.rn.f32x2 %0, %1, %2, %0;" : "+l"(d) : "l"(a), "l"(b));
}
__device__ __forceinline__ ull add2(ull a, ull b) {
    ull d; asm("add.rn.f32x2 %0, %1, %2;" : "=l"(d) : "l"(a), "l"(b)); return d;
}
__device__ __forceinline__ float2 unpack2(ull u) {
    float2 r; asm("mov.b64 {%0, %1}, %2;" : "=f"(r.x), "=f"(r.y) : "l"(u)); return r;
}
__device__ __forceinline__ ull pack2(float lo, float hi) {
    ull d; asm("mov.b64 %0, {%1, %2};" : "=l"(d) : "f"(lo), "f"(hi)); return d;
}
__device__ __forceinline__ float tanh_approx(float x) {
    float r; asm("tanh.approx.f32 %0, %1;" : "=f"(r) : "f"(x)); return r;
}

// ---------- Kernel 1: xW = input @ Wi^T + bi, written into out[S,128] ----------
__global__ void __launch_bounds__(128) gemm_xw_kernel(
    const float* __restrict__ X,   // [S, 256]
    const float* __restrict__ Wi,  // [128, 256]
    const float* __restrict__ bi,  // [128]
    float* __restrict__ out, int S)
{
    __shared__ __align__(16) float xs[32][DD];
    const int h  = threadIdx.x;
    const int s0 = blockIdx.x * 32;

    const float4* Xg  = (const float4*)(X + (size_t)s0 * DD);
    float4*       xs4 = (float4*)&xs[0][0];
#pragma unroll
    for (int i = 0; i < 16; i++) xs4[h + 128 * i] = Xg[h + 128 * i];
    __syncthreads();

    float acc[32];
#pragma unroll
    for (int s = 0; s < 32; s++) acc[s] = 0.f;

    const float4* wr = (const float4*)(Wi + h * DD);
#pragma unroll 4
    for (int kk = 0; kk < DD / 4; kk++) {
        float4 wv = wr[kk];
#pragma unroll
        for (int s = 0; s < 32; s++) {
            float4 xv = *(const float4*)&xs[s][kk * 4];
            acc[s] = fmaf(wv.x, xv.x, acc[s]);
            acc[s] = fmaf(wv.y, xv.y, acc[s]);
            acc[s] = fmaf(wv.z, xv.z, acc[s]);
            acc[s] = fmaf(wv.w, xv.w, acc[s]);
        }
    }
    const float b = bi[h];
#pragma unroll
    for (int s = 0; s < 32; s++) out[(size_t)(s0 + s) * HD + h] = acc[s] + b;
}

// ---------- Kernel 2: sequential recurrence ----------
// 128 threads = 4 warps (1/SMSP). Lane j owns output j, full Wh row j in
// registers (64 f32x2). h double-buffered in shared; reads are broadcast
// LDS.128. Latency-bound design: no shfl, in-lane 8-acc reduce tree,
// tanh via single MUFU, xw+bias folded into accumulator init, loads
// software-pipelined in 4-LDS chunks against the FFMA2 stream.
// One __syncthreads per step; xw rows prefetched 8 steps ahead
// (L2-resident); h stream overwrites consumed xw rows in d_out.
__global__ void __launch_bounds__(128, 1) rnn_seq_kernel(
    const float* __restrict__ Wh,  // [128, 128]
    const float* __restrict__ bh,  // [128]
    const float* __restrict__ h0,  // [1, 128]
    float* out,                    // [S, 128]: xw in, h out
    float* hn, int S, int has_hn)
{
    __shared__ __align__(16) float sh[2][HD];
    const int j = threadIdx.x;

    // full Wh row j in registers: 64 packed f32x2
    ull w[64];
    {
        const ulonglong2* wp = (const ulonglong2*)(Wh + j * HD);
#pragma unroll
        for (int i = 0; i < 32; i++) { ulonglong2 v = wp[i]; w[2*i] = v.x; w[2*i+1] = v.y; }
    }
    const float bj = bh[j];

    sh[0][j] = h0[j];

    float xwb[8], xwn[8];
#pragma unroll
    for (int q = 0; q < 8; q++) xwb[q] = out[q * HD + j] + bj;

    __syncthreads();

    for (int t = 0; t < S; t += 8) {
        // prefetch the next 8 xw rows (consumed next outer iteration)
#pragma unroll
        for (int q = 0; q < 8; q++) {
            int tn = t + 8 + q;
            xwn[q] = (tn < S) ? out[(size_t)tn * HD + j] : 0.f;
        }
#pragma unroll
        for (int q = 0; q < 8; q++) {
            const int buf  = q & 1;        // t % 8 == 0, so step parity == q parity
            const int nbuf = buf ^ 1;
            const ulonglong2* hp = (const ulonglong2*)(&sh[buf][0]);

            // a0 seeded with (xw + bias) -> no post-reduce add on the chain
            ull a0 = pack2(xwb[q], 0.0f);
            ull a1 = 0, a2 = 0, a3 = 0, a4 = 0, a5 = 0, a6 = 0, a7 = 0;

            // software-pipelined: prefetch chunk 0, then load i+1 while fma i
            ulonglong2 c0 = hp[0], c1 = hp[1], c2 = hp[2], c3 = hp[3];
#pragma unroll
            for (int i = 0; i < 8; i++) {
                ulonglong2 n0, n1, n2, n3;
                if (i < 7) { n0 = hp[4*i+4]; n1 = hp[4*i+5]; n2 = hp[4*i+6]; n3 = hp[4*i+7]; }
                fma2(a0, w[8*i + 0], c0.x);
                fma2(a1, w[8*i + 1], c0.y);
                fma2(a2, w[8*i + 2], c1.x);
                fma2(a3, w[8*i + 3], c1.y);
                fma2(a4, w[8*i + 4], c2.x);
                fma2(a5, w[8*i + 5], c2.y);
                fma2(a6, w[8*i + 6], c3.x);
                fma2(a7, w[8*i + 7], c3.y);
                if (i < 7) { c0 = n0; c1 = n1; c2 = n2; c3 = n3; }
            }
            // 3-level packed reduce, horizontal add, MUFU tanh
            ull s0 = add2(a0, a1), s1 = add2(a2, a3), s2 = add2(a4, a5), s3 = add2(a6, a7);
            float2 rr = unpack2(add2(add2(s0, s1), add2(s2, s3)));
            float hval = tanh_approx(rr.x + rr.y);

            sh[nbuf][j] = hval;                        // publish h_t
            out[(size_t)(t + q) * HD + j] = hval;      // coalesced stream to gmem
            __syncthreads();
        }
#pragma unroll
        for (int q = 0; q < 8; q++) xwb[q] = xwn[q] + bj;
    }

    if (has_hn) hn[j] = sh[S & 1][j];
}

// ---------- launcher ----------
extern "C" void kernel_launch(void* const* d_in, const int* in_sizes, int n_in,
                              void* d_out, int out_size)
{
    (void)n_in;
    const float* input = (const float*)d_in[0];  // [S, 256]
    const float* h0    = (const float*)d_in[1];  // [1, 128]
    const float* Wi    = (const float*)d_in[2];  // [128, 256]
    const float* bi    = (const float*)d_in[3];  // [128]
    const float* Wh    = (const float*)d_in[4];  // [128, 128]
    const float* bh    = (const float*)d_in[5];  // [128]
    float* out = (float*)d_out;

    const int S = in_sizes[0] / DD;
    const int has_hn = (out_size >= S * HD + HD) ? 1 : 0;
    float* hn = out + (size_t)S * HD;

    gemm_xw_kernel<<<(S + 31) / 32, 128>>>(input, Wi, bi, out, S);
    rnn_seq_kernel<<<1, 128>>>(Wh, bh, h0, out, hn, S, has_hn);
}

// round 8
// speedup vs baseline: 1.6512x; 1.0312x over previous
#include <cuda_runtime.h>
#include <cstdint>

typedef unsigned long long ull;

#define HD 128
#define DD 256

// ---------- packed f32x2 helpers (Blackwell sm_100+) ----------
__device__ __forceinline__ void fma2(ull &d, ull a, ull b) {
    asm("fma.rn.f32x2 %0, %1, %2, %0;" : "+l"(d) : "l"(a), "l"(b));
}
__device__ __forceinline__ ull add2(ull a, ull b) {
    ull d; asm("add.rn.f32x2 %0, %1, %2;" : "=l"(d) : "l"(a), "l"(b)); return d;
}
__device__ __forceinline__ float2 unpack2(ull u) {
    float2 r; asm("mov.b64 {%0, %1}, %2;" : "=f"(r.x), "=f"(r.y) : "l"(u)); return r;
}
__device__ __forceinline__ ull pack2(float lo, float hi) {
    ull d; asm("mov.b64 %0, {%1, %2};" : "=l"(d) : "f"(lo), "f"(hi)); return d;
}
__device__ __forceinline__ float tanh_approx(float x) {
    float r; asm("tanh.approx.f32 %0, %1;" : "=f"(r) : "f"(x)); return r;
}

// ---------- Kernel 1: xW = input @ Wi^T + bi, written into out[S,128] ----------
__global__ void __launch_bounds__(128) gemm_xw_kernel(
    const float* __restrict__ X,   // [S, 256]
    const float* __restrict__ Wi,  // [128, 256]
    const float* __restrict__ bi,  // [128]
    float* __restrict__ out, int S)
{
    __shared__ __align__(16) float xs[32][DD];
    const int h  = threadIdx.x;
    const int s0 = blockIdx.x * 32;

    const float4* Xg  = (const float4*)(X + (size_t)s0 * DD);
    float4*       xs4 = (float4*)&xs[0][0];
#pragma unroll
    for (int i = 0; i < 16; i++) xs4[h + 128 * i] = Xg[h + 128 * i];
    __syncthreads();

    float acc[32];
#pragma unroll
    for (int s = 0; s < 32; s++) acc[s] = 0.f;

    const float4* wr = (const float4*)(Wi + h * DD);
#pragma unroll 4
    for (int kk = 0; kk < DD / 4; kk++) {
        float4 wv = wr[kk];
#pragma unroll
        for (int s = 0; s < 32; s++) {
            float4 xv = *(const float4*)&xs[s][kk * 4];
            acc[s] = fmaf(wv.x, xv.x, acc[s]);
            acc[s] = fmaf(wv.y, xv.y, acc[s]);
            acc[s] = fmaf(wv.z, xv.z, acc[s]);
            acc[s] = fmaf(wv.w, xv.w, acc[s]);
        }
    }
    const float b = bi[h];
#pragma unroll
    for (int s = 0; s < 32; s++) out[(size_t)(s0 + s) * HD + h] = acc[s] + b;
}

// ---------- Kernel 2: sequential recurrence ----------
// 128 threads = 4 warps (1/SMSP). Lane j owns output j, full Wh row j in
// registers (64 f32x2). h double-buffered in shared; reads are broadcast
// LDS.128. Depth-2 software pipeline: load chunk i+2 while FMA-ing chunk i
// (2 chunks of FMA issue cover the 29-cyc LDS latency). 4 accumulators
// (2-level reduce tree), xw+bias folded into a0's seed, tanh via single
// MUFU, gmem h stores batched outside the 8-step inner loop.
// One __syncthreads per step; xw rows prefetched 8 steps ahead.
__global__ void __launch_bounds__(128, 1) rnn_seq_kernel(
    const float* __restrict__ Wh,  // [128, 128]
    const float* __restrict__ bh,  // [128]
    const float* __restrict__ h0,  // [1, 128]
    float* out,                    // [S, 128]: xw in, h out
    float* hn, int S, int has_hn)
{
    __shared__ __align__(16) float sh[2][HD];
    const int j = threadIdx.x;

    // full Wh row j in registers: 64 packed f32x2
    ull w[64];
    {
        const ulonglong2* wp = (const ulonglong2*)(Wh + j * HD);
#pragma unroll
        for (int i = 0; i < 32; i++) { ulonglong2 v = wp[i]; w[2*i] = v.x; w[2*i+1] = v.y; }
    }
    const float bj = bh[j];

    sh[0][j] = h0[j];

    float xwb[8], xwn[8], hv[8];
#pragma unroll
    for (int q = 0; q < 8; q++) xwb[q] = out[q * HD + j] + bj;

    __syncthreads();

    for (int t = 0; t < S; t += 8) {
        // prefetch the next 8 xw rows (consumed next outer iteration)
#pragma unroll
        for (int q = 0; q < 8; q++) {
            int tn = t + 8 + q;
            xwn[q] = (tn < S) ? out[(size_t)tn * HD + j] : 0.f;
        }
#pragma unroll
        for (int q = 0; q < 8; q++) {
            const int buf  = q & 1;        // t % 8 == 0, so step parity == q parity
            const int nbuf = buf ^ 1;
            const ulonglong2* hp = (const ulonglong2*)(&sh[buf][0]);

            // a0 seeded with (xw + bias) -> no post-reduce add on the chain
            ull a0 = pack2(xwb[q], 0.0f);
            ull a1 = 0, a2 = 0, a3 = 0;

            // depth-2 pipeline: chunks 0 and 1 preloaded; load i+2 while fma i
            ulonglong2 A0 = hp[0], A1 = hp[1], A2 = hp[2], A3 = hp[3];
            ulonglong2 B0 = hp[4], B1 = hp[5], B2 = hp[6], B3 = hp[7];
#pragma unroll
            for (int i = 0; i < 8; i++) {
                ulonglong2 N0, N1, N2, N3;
                if (i < 6) {
                    N0 = hp[4*i +  8]; N1 = hp[4*i +  9];
                    N2 = hp[4*i + 10]; N3 = hp[4*i + 11];
                }
                fma2(a0, w[8*i + 0], A0.x);
                fma2(a1, w[8*i + 1], A0.y);
                fma2(a2, w[8*i + 2], A1.x);
                fma2(a3, w[8*i + 3], A1.y);
                fma2(a0, w[8*i + 4], A2.x);
                fma2(a1, w[8*i + 5], A2.y);
                fma2(a2, w[8*i + 6], A3.x);
                fma2(a3, w[8*i + 7], A3.y);
                A0 = B0; A1 = B1; A2 = B2; A3 = B3;
                if (i < 6) { B0 = N0; B1 = N1; B2 = N2; B3 = N3; }
            }
            // 2-level packed reduce, horizontal add, MUFU tanh
            float2 rr = unpack2(add2(add2(a0, a1), add2(a2, a3)));
            float hval = tanh_approx(rr.x + rr.y);
            hv[q] = hval;

            sh[nbuf][j] = hval;       // publish h_t (only STS on the chain)
            __syncthreads();
        }
        // batched gmem stream of the 8 h rows (overlaps next prefetch)
#pragma unroll
        for (int q = 0; q < 8; q++) out[(size_t)(t + q) * HD + j] = hv[q];
#pragma unroll
        for (int q = 0; q < 8; q++) xwb[q] = xwn[q] + bj;
    }

    if (has_hn) hn[j] = hv[7];
}

// ---------- launcher ----------
extern "C" void kernel_launch(void* const* d_in, const int* in_sizes, int n_in,
                              void* d_out, int out_size)
{
    (void)n_in;
    const float* input = (const float*)d_in[0];  // [S, 256]
    const float* h0    = (const float*)d_in[1];  // [1, 128]
    const float* Wi    = (const float*)d_in[2];  // [128, 256]
    const float* bi    = (const float*)d_in[3];  // [128]
    const float* Wh    = (const float*)d_in[4];  // [128, 128]
    const float* bh    = (const float*)d_in[5];  // [128]
    float* out = (float*)d_out;

    const int S = in_sizes[0] / DD;
    const int has_hn = (out_size >= S * HD + HD) ? 1 : 0;
    float* hn = out + (size_t)S * HD;

    gemm_xw_kernel<<<(S + 31) / 32, 128>>>(input, Wi, bi, out, S);
    rnn_seq_kernel<<<1, 128>>>(Wh, bh, h0, out, hn, S, has_hn);
}

// round 9
// speedup vs baseline: 1.7489x; 1.0592x over previous
#include <cuda_runtime.h>
#include <cstdint>

typedef unsigned long long ull;

#define HD 128
#define DD 256

// ---------- packed f32x2 helpers (Blackwell sm_100+) ----------
__device__ __forceinline__ void fma2(ull &d, ull a, ull b) {
    asm("fma.rn.f32x2 %0, %1, %2, %0;" : "+l"(d) : "l"(a), "l"(b));
}
__device__ __forceinline__ ull add2(ull a, ull b) {
    ull d; asm("add.rn.f32x2 %0, %1, %2;" : "=l"(d) : "l"(a), "l"(b)); return d;
}
__device__ __forceinline__ float2 unpack2(ull u) {
    float2 r; asm("mov.b64 {%0, %1}, %2;" : "=f"(r.x), "=f"(r.y) : "l"(u)); return r;
}
__device__ __forceinline__ ull pack2(float lo, float hi) {
    ull d; asm("mov.b64 %0, {%1, %2};" : "=l"(d) : "f"(lo), "f"(hi)); return d;
}
__device__ __forceinline__ float tanh_approx(float x) {
    float r; asm("tanh.approx.f32 %0, %1;" : "=f"(r) : "f"(x)); return r;
}

// ---------- Kernel 1: xW = input @ Wi^T + bi, written into out[S,128] ----------
__global__ void __launch_bounds__(128) gemm_xw_kernel(
    const float* __restrict__ X,   // [S, 256]
    const float* __restrict__ Wi,  // [128, 256]
    const float* __restrict__ bi,  // [128]
    float* __restrict__ out, int S)
{
    __shared__ __align__(16) float xs[32][DD];
    const int h  = threadIdx.x;
    const int s0 = blockIdx.x * 32;

    const float4* Xg  = (const float4*)(X + (size_t)s0 * DD);
    float4*       xs4 = (float4*)&xs[0][0];
#pragma unroll
    for (int i = 0; i < 16; i++) xs4[h + 128 * i] = Xg[h + 128 * i];
    __syncthreads();

    float acc[32];
#pragma unroll
    for (int s = 0; s < 32; s++) acc[s] = 0.f;

    const float4* wr = (const float4*)(Wi + h * DD);
#pragma unroll 4
    for (int kk = 0; kk < DD / 4; kk++) {
        float4 wv = wr[kk];
#pragma unroll
        for (int s = 0; s < 32; s++) {
            float4 xv = *(const float4*)&xs[s][kk * 4];
            acc[s] = fmaf(wv.x, xv.x, acc[s]);
            acc[s] = fmaf(wv.y, xv.y, acc[s]);
            acc[s] = fmaf(wv.z, xv.z, acc[s]);
            acc[s] = fmaf(wv.w, xv.w, acc[s]);
        }
    }
    const float b = bi[h];
#pragma unroll
    for (int s = 0; s < 32; s++) out[(size_t)(s0 + s) * HD + h] = acc[s] + b;
}

// ---------- Kernel 2: sequential recurrence ----------
// 128 threads = 4 warps (1/SMSP). Lane j owns output j; full Wh row j in
// registers, PRE-ROTATED so register group g corresponds to K-group
// kg = (2*wrp + g) & 7. Each step: warp w's OWN 32 h-values (K-groups
// 2w, 2w+1) were preloaded into registers PRE-BARRIER (STS -> syncwarp ->
// LDS own segment), so post-barrier FMA starts immediately from registers;
// the 6 foreign K-groups are loaded with depth-2 lookahead under the FMA
// stream. 4 accumulators, xw+bias seeded into a0, MUFU tanh, batched STG.
__global__ void __launch_bounds__(128, 1) rnn_seq_kernel(
    const float* __restrict__ Wh,  // [128, 128]
    const float* __restrict__ bh,  // [128]
    const float* __restrict__ h0,  // [1, 128]
    float* out,                    // [S, 128]: xw in, h out
    float* hn, int S, int has_hn)
{
    __shared__ __align__(16) float sh[2][HD];
    const int j   = threadIdx.x;
    const int wrp = j >> 5;

    // pre-rotated weights: register group g <-> K-group (2*wrp+g)&7
    ull w[64];
#pragma unroll
    for (int g = 0; g < 8; g++) {
        const int kg = (2 * wrp + g) & 7;
        const ulonglong2* wp = (const ulonglong2*)(Wh + j * HD + kg * 16);
#pragma unroll
        for (int u = 0; u < 4; u++) {
            ulonglong2 v = wp[u];
            w[8 * g + 2 * u]     = v.x;
            w[8 * g + 2 * u + 1] = v.y;
        }
    }
    const float bj = bh[j];

    sh[0][j] = h0[j];

    float xwb[8], xwn[8], hv[8];
#pragma unroll
    for (int q = 0; q < 8; q++) xwb[q] = out[q * HD + j] + bj;

    __syncthreads();

    // preload own segment (K-groups 2w,2w+1 = rotated groups 0,1) of buf 0
    ull own[16];
    {
        const ulonglong2* op = (const ulonglong2*)(&sh[0][wrp * 32]);
#pragma unroll
        for (int u = 0; u < 8; u++) { ulonglong2 v = op[u]; own[2*u] = v.x; own[2*u+1] = v.y; }
    }

    for (int t = 0; t < S; t += 8) {
        // prefetch the next 8 xw rows (consumed next outer iteration)
#pragma unroll
        for (int q = 0; q < 8; q++) {
            int tn = t + 8 + q;
            xwn[q] = (tn < S) ? out[(size_t)tn * HD + j] : 0.f;
        }
#pragma unroll
        for (int q = 0; q < 8; q++) {
            const int buf  = q & 1;        // t % 8 == 0, so step parity == q parity
            const int nbuf = buf ^ 1;
            const float* hb = &sh[buf][0];

            // foreign groups, depth-2 lookahead (rotated groups 2..7)
            const ulonglong2* g2p = (const ulonglong2*)(hb + (((2*wrp + 2) & 7) << 4));
            const ulonglong2* g3p = (const ulonglong2*)(hb + (((2*wrp + 3) & 7) << 4));
            ulonglong2 A0 = g2p[0], A1 = g2p[1], A2 = g2p[2], A3 = g2p[3];
            ulonglong2 B0 = g3p[0], B1 = g3p[1], B2 = g3p[2], B3 = g3p[3];

            // a0 seeded with (xw + bias)
            ull a0 = pack2(xwb[q], 0.0f);
            ull a1 = 0, a2 = 0, a3 = 0;

            // own groups first: 16 FFMA2 straight from registers
#pragma unroll
            for (int u = 0; u < 4; u++) {
                fma2(a0, w[4*u + 0], own[4*u + 0]);
                fma2(a1, w[4*u + 1], own[4*u + 1]);
                fma2(a2, w[4*u + 2], own[4*u + 2]);
                fma2(a3, w[4*u + 3], own[4*u + 3]);
            }
            // foreign groups 2..7
#pragma unroll
            for (int g = 2; g < 8; g++) {
                ulonglong2 N0, N1, N2, N3;
                if (g < 6) {
                    const ulonglong2* np = (const ulonglong2*)(hb + (((2*wrp + g + 2) & 7) << 4));
                    N0 = np[0]; N1 = np[1]; N2 = np[2]; N3 = np[3];
                }
                fma2(a0, w[8*g + 0], A0.x);
                fma2(a1, w[8*g + 1], A0.y);
                fma2(a2, w[8*g + 2], A1.x);
                fma2(a3, w[8*g + 3], A1.y);
                fma2(a0, w[8*g + 4], A2.x);
                fma2(a1, w[8*g + 5], A2.y);
                fma2(a2, w[8*g + 6], A3.x);
                fma2(a3, w[8*g + 7], A3.y);
                A0 = B0; A1 = B1; A2 = B2; A3 = B3;
                if (g < 6) { B0 = N0; B1 = N1; B2 = N2; B3 = N3; }
            }
            // 2-level packed reduce, horizontal add, MUFU tanh
            float2 rr = unpack2(add2(add2(a0, a1), add2(a2, a3)));
            float hval = tanh_approx(rr.x + rr.y);
            hv[q] = hval;

            sh[nbuf][j] = hval;       // publish h_t
            __syncwarp();
            // pre-bar preload of OWN segment of the next buffer (this warp's
            // 32 values, just written by its own lanes -> warp-coherent)
            {
                const ulonglong2* op = (const ulonglong2*)(&sh[nbuf][wrp * 32]);
#pragma unroll
                for (int u = 0; u < 8; u++) { ulonglong2 v = op[u]; own[2*u] = v.x; own[2*u+1] = v.y; }
            }
            __syncthreads();
        }
        // batched gmem stream of the 8 h rows (overlaps next prefetch)
#pragma unroll
        for (int q = 0; q < 8; q++) out[(size_t)(t + q) * HD + j] = hv[q];
#pragma unroll
        for (int q = 0; q < 8; q++) xwb[q] = xwn[q] + bj;
    }

    if (has_hn) hn[j] = hv[7];
}

// ---------- launcher ----------
extern "C" void kernel_launch(void* const* d_in, const int* in_sizes, int n_in,
                              void* d_out, int out_size)
{
    (void)n_in;
    const float* input = (const float*)d_in[0];  // [S, 256]
    const float* h0    = (const float*)d_in[1];  // [1, 128]
    const float* Wi    = (const float*)d_in[2];  // [128, 256]
    const float* bi    = (const float*)d_in[3];  // [128]
    const float* Wh    = (const float*)d_in[4];  // [128, 128]
    const float* bh    = (const float*)d_in[5];  // [128]
    float* out = (float*)d_out;

    const int S = in_sizes[0] / DD;
    const int has_hn = (out_size >= S * HD + HD) ? 1 : 0;
    float* hn = out + (size_t)S * HD;

    gemm_xw_kernel<<<(S + 31) / 32, 128>>>(input, Wi, bi, out, S);
    rnn_seq_kernel<<<1, 128>>>(Wh, bh, h0, out, hn, S, has_hn);
}